// round 3
// baseline (speedup 1.0000x reference)
#include <cuda_runtime.h>
#include <cstdint>

// Problem constants (fixed by the dataset)
#define MAXN 100000
#define MAXE 1600000

// ---------------- scratch (device globals; no allocs allowed) ----------------
__device__ float g_m[MAXN * 64];      // pool-transformed features
__device__ float g_agg[MAXN * 64];    // max-aggregated features
__device__ float g_h1[MAXN * 64];     // layer-1 output
__device__ float g_h2[MAXN * 32];     // layer-2 output
__device__ float g_agg3[MAXN * 32];   // layer-3 mean aggregate
__device__ int   g_rowptr[MAXN + 1];
__device__ int   g_deg[MAXN];         // degree, then reused as scatter cursor
__device__ int   g_scantmp[MAXN];
__device__ int   g_bsum[1024];
__device__ int   g_csrc[MAXE];        // CSR src ids, grouped by dst

// ---------------- CSR build ----------------
__global__ void k_zero_int(int* p, int n) {
    int i = blockIdx.x * blockDim.x + threadIdx.x;
    if (i < n) p[i] = 0;
}

__global__ void k_hist(const int* __restrict__ dst, int* __restrict__ deg, int E, int N) {
    int e = blockIdx.x * blockDim.x + threadIdx.x;
    if (e < E) {
        int d = dst[e];
        if (d >= 0 && d < N) atomicAdd(&deg[d], 1);
    }
}

// pass 1: per-block inclusive scan (512 elems / block)
__global__ void k_scan1(const int* __restrict__ deg, int* __restrict__ scantmp,
                        int* __restrict__ bsum, int n) {
    __shared__ int sh[512];
    int tid = threadIdx.x;
    int i = blockIdx.x * 512 + tid;
    int v = (i < n) ? deg[i] : 0;
    sh[tid] = v;
    __syncthreads();
#pragma unroll
    for (int off = 1; off < 512; off <<= 1) {
        int t = (tid >= off) ? sh[tid - off] : 0;
        __syncthreads();
        sh[tid] += t;
        __syncthreads();
    }
    if (i < n) scantmp[i] = sh[tid];
    if (tid == 511) bsum[blockIdx.x] = sh[511];
}

// pass 2: exclusive scan of block sums (tiny)
__global__ void k_scan2(int* bsum, int nb) {
    if (threadIdx.x == 0 && blockIdx.x == 0) {
        int run = 0;
        for (int b = 0; b < nb; b++) { int t = bsum[b]; bsum[b] = run; run += t; }
    }
}

// pass 3: exclusive rowptr + cursor init (deg array becomes cursor)
__global__ void k_scan3(const int* __restrict__ scantmp, int* __restrict__ deg_cursor,
                        int* __restrict__ rowptr, const int* __restrict__ bsum,
                        int n, int E) {
    int i = blockIdx.x * blockDim.x + threadIdx.x;
    if (i < n) {
        int d = deg_cursor[i];
        int ex = scantmp[i] - d + bsum[i >> 9];
        rowptr[i] = ex;
        deg_cursor[i] = ex;   // cursor
    }
    if (i == 0) rowptr[n] = E;
}

__global__ void k_scatter(const int* __restrict__ src, const int* __restrict__ dst,
                          int* __restrict__ cursor, int* __restrict__ csrc, int E, int N) {
    int e = blockIdx.x * blockDim.x + threadIdx.x;
    if (e < E) {
        int d = dst[e];
        if (d >= 0 && d < N) {
            int p = atomicAdd(&cursor[d], 1);
            csrc[p] = src[e];
        }
    }
}

// ---------------- aggregation (gather over CSR, warp per node) ----------------
// max over relu'd features (all >= 0 so init 0 matches reference incl. isolated nodes)
__global__ void k_agg_max64(const float* __restrict__ feat, float* __restrict__ out,
                            const int* __restrict__ rowptr, const int* __restrict__ srcs,
                            int n) {
    int v = blockIdx.x * (blockDim.x >> 5) + (threadIdx.x >> 5);
    if (v >= n) return;
    int lane = threadIdx.x & 31;
    int beg = rowptr[v], end = rowptr[v + 1];
    float a0 = 0.f, a1 = 0.f;
    int e = beg;
    for (; e + 1 < end; e += 2) {
        int s0 = __ldg(&srcs[e]);
        int s1 = __ldg(&srcs[e + 1]);
        const float* f0 = feat + (size_t)s0 * 64;
        const float* f1 = feat + (size_t)s1 * 64;
        float b0 = f0[lane], b1 = f0[lane + 32];
        float c0 = f1[lane], c1 = f1[lane + 32];
        a0 = fmaxf(a0, fmaxf(b0, c0));
        a1 = fmaxf(a1, fmaxf(b1, c1));
    }
    if (e < end) {
        int s0 = __ldg(&srcs[e]);
        const float* f0 = feat + (size_t)s0 * 64;
        a0 = fmaxf(a0, f0[lane]);
        a1 = fmaxf(a1, f0[lane + 32]);
    }
    out[(size_t)v * 64 + lane] = a0;
    out[(size_t)v * 64 + 32 + lane] = a1;
}

// mean over 32-dim features (count == degree == rowptr diff)
__global__ void k_agg_mean32(const float* __restrict__ feat, float* __restrict__ out,
                             const int* __restrict__ rowptr, const int* __restrict__ srcs,
                             int n) {
    int v = blockIdx.x * (blockDim.x >> 5) + (threadIdx.x >> 5);
    if (v >= n) return;
    int lane = threadIdx.x & 31;
    int beg = rowptr[v], end = rowptr[v + 1];
    float a = 0.f;
    int e = beg;
    for (; e + 1 < end; e += 2) {
        int s0 = __ldg(&srcs[e]);
        int s1 = __ldg(&srcs[e + 1]);
        a += feat[(size_t)s0 * 32 + lane];
        a += feat[(size_t)s1 * 32 + lane];
    }
    if (e < end) {
        int s0 = __ldg(&srcs[e]);
        a += feat[(size_t)s0 * 32 + lane];
    }
    float cnt = (float)(end - beg);
    float inv = 1.f / fmaxf(cnt, 1.f);
    out[(size_t)v * 32 + lane] = a * inv;
}

// ---------------- fused node GEMM ----------------
// out = [relu]( A@W1 [+ B@W2] + bias ), A/B: [n, IN] row-major, W: [IN, OUT] row-major
// 256 threads; 256 nodes per block; per-thread register tile 8 nodes x (OUT/8) outs.
template <int IN, int OUT, bool RELU, bool TWO>
__global__ void __launch_bounds__(256) k_gemm(const float* __restrict__ A,
                                              const float* __restrict__ W1,
                                              const float* __restrict__ B,
                                              const float* __restrict__ W2,
                                              const float* __restrict__ bias,
                                              float* __restrict__ out, int n) {
    constexpr int NPB = 256;
    constexpr int TJ = OUT / 8;   // outputs per thread; 8 j-groups
    constexpr int LDA = IN + 1;   // pad to avoid bank conflicts on node reads
    extern __shared__ float sm[];
    float* sW1 = sm;                                // IN*OUT
    float* sW2 = TWO ? (sm + IN * OUT) : nullptr;   // IN*OUT
    float* sB = sm + IN * OUT * (TWO ? 2 : 1);      // OUT
    float* sA = sB + OUT;                           // NPB*LDA

    int tid = threadIdx.x;
    for (int i = tid; i < IN * OUT; i += 256) {
        sW1[i] = W1[i];
        if (TWO) sW2[i] = W2[i];
    }
    for (int i = tid; i < OUT; i += 256) sB[i] = bias[i];

    int base = blockIdx.x * NPB;
    for (int i = tid; i < NPB * IN; i += 256) {
        int nn = i / IN, kk = i % IN;
        sA[nn * LDA + kk] = (base + nn < n) ? A[(size_t)(base + nn) * IN + kk] : 0.f;
    }
    __syncthreads();

    int jg = tid & 7;
    int ng = tid >> 3;  // 0..31, each owns 8 nodes
    float acc[8][TJ];
#pragma unroll
    for (int i = 0; i < 8; i++)
#pragma unroll
        for (int j = 0; j < TJ; j++) acc[i][j] = 0.f;

    const float* sAr = sA + (ng * 8) * LDA;
#pragma unroll 8
    for (int k = 0; k < IN; k++) {
        float xv[8];
#pragma unroll
        for (int i = 0; i < 8; i++) xv[i] = sAr[i * LDA + k];
        float wv[TJ];
#pragma unroll
        for (int j = 0; j < TJ; j++) wv[j] = sW1[k * OUT + jg * TJ + j];
#pragma unroll
        for (int i = 0; i < 8; i++)
#pragma unroll
            for (int j = 0; j < TJ; j++) acc[i][j] = fmaf(xv[i], wv[j], acc[i][j]);
    }

    if (TWO) {
        __syncthreads();
        for (int i = tid; i < NPB * IN; i += 256) {
            int nn = i / IN, kk = i % IN;
            sA[nn * LDA + kk] = (base + nn < n) ? B[(size_t)(base + nn) * IN + kk] : 0.f;
        }
        __syncthreads();
#pragma unroll 8
        for (int k = 0; k < IN; k++) {
            float xv[8];
#pragma unroll
            for (int i = 0; i < 8; i++) xv[i] = sAr[i * LDA + k];
            float wv[TJ];
#pragma unroll
            for (int j = 0; j < TJ; j++) wv[j] = sW2[k * OUT + jg * TJ + j];
#pragma unroll
            for (int i = 0; i < 8; i++)
#pragma unroll
                for (int j = 0; j < TJ; j++) acc[i][j] = fmaf(xv[i], wv[j], acc[i][j]);
        }
    }

#pragma unroll
    for (int i = 0; i < 8; i++) {
        int node = base + ng * 8 + i;
        if (node < n) {
#pragma unroll
            for (int j = 0; j < TJ; j++) {
                float v = acc[i][j] + sB[jg * TJ + j];
                if (RELU) v = fmaxf(v, 0.f);
                out[(size_t)node * OUT + jg * TJ + j] = v;
            }
        }
    }
}

// ---------------- host launch ----------------
static inline int smem_bytes(int IN, int OUT, bool TWO) {
    return (IN * OUT * (TWO ? 2 : 1) + OUT + 256 * (IN + 1)) * (int)sizeof(float);
}

extern "C" void kernel_launch(void* const* d_in, const int* in_sizes, int n_in,
                              void* d_out, int out_size) {
    const float* x        = (const float*)d_in[0];
    const int*   ei       = (const int*)d_in[1];   // int32! (JAX x64 disabled)
    const float* W1_pool  = (const float*)d_in[2];
    const float* b1_pool  = (const float*)d_in[3];
    const float* W1_self  = (const float*)d_in[4];
    const float* W1_neigh = (const float*)d_in[5];
    const float* b1       = (const float*)d_in[6];
    const float* W2_pool  = (const float*)d_in[7];
    const float* b2_pool  = (const float*)d_in[8];
    const float* W2_self  = (const float*)d_in[9];
    const float* W2_neigh = (const float*)d_in[10];
    const float* b2       = (const float*)d_in[11];
    const float* W3_self  = (const float*)d_in[12];
    const float* W3_neigh = (const float*)d_in[13];
    const float* b3       = (const float*)d_in[14];

    int N = in_sizes[0] / 64;
    int E = in_sizes[1] / 2;
    if (N > MAXN) N = MAXN;
    if (E > MAXE) E = MAXE;

    const int* src = ei;        // row 0
    const int* dst = ei + E;    // row 1

    // scratch pointers
    float *m, *agg, *h1, *h2, *agg3;
    int *rowptr, *deg, *scantmp, *bsum, *csrc;
    cudaGetSymbolAddress((void**)&m, g_m);
    cudaGetSymbolAddress((void**)&agg, g_agg);
    cudaGetSymbolAddress((void**)&h1, g_h1);
    cudaGetSymbolAddress((void**)&h2, g_h2);
    cudaGetSymbolAddress((void**)&agg3, g_agg3);
    cudaGetSymbolAddress((void**)&rowptr, g_rowptr);
    cudaGetSymbolAddress((void**)&deg, g_deg);
    cudaGetSymbolAddress((void**)&scantmp, g_scantmp);
    cudaGetSymbolAddress((void**)&bsum, g_bsum);
    cudaGetSymbolAddress((void**)&csrc, g_csrc);

    // dynamic smem attributes for GEMM instantiations (idempotent)
    cudaFuncSetAttribute((const void*)k_gemm<64, 64, true, false>,
                         cudaFuncAttributeMaxDynamicSharedMemorySize, smem_bytes(64, 64, false));
    cudaFuncSetAttribute((const void*)k_gemm<64, 64, true, true>,
                         cudaFuncAttributeMaxDynamicSharedMemorySize, smem_bytes(64, 64, true));
    cudaFuncSetAttribute((const void*)k_gemm<64, 32, false, true>,
                         cudaFuncAttributeMaxDynamicSharedMemorySize, smem_bytes(64, 32, true));
    cudaFuncSetAttribute((const void*)k_gemm<32, 32, false, true>,
                         cudaFuncAttributeMaxDynamicSharedMemorySize, smem_bytes(32, 32, true));

    int ethreads = 256;
    int eblocks = (E + ethreads - 1) / ethreads;
    int nblocks256 = (N + 255) / 256;
    int nbScan = (N + 511) / 512;
    int aggBlocks = (N + 7) / 8;  // 8 warps / block

    // ---- CSR build ----
    k_zero_int<<<nblocks256, 256>>>(deg, N);
    k_hist<<<eblocks, ethreads>>>(dst, deg, E, N);
    k_scan1<<<nbScan, 512>>>(deg, scantmp, bsum, N);
    k_scan2<<<1, 32>>>(bsum, nbScan);
    k_scan3<<<nblocks256, 256>>>(scantmp, deg, rowptr, bsum, N, E);
    k_scatter<<<eblocks, ethreads>>>(src, dst, deg, csrc, E, N);

    // ---- layer 1 (pool) ----
    k_gemm<64, 64, true, false><<<nblocks256, 256, smem_bytes(64, 64, false)>>>(
        x, W1_pool, nullptr, nullptr, b1_pool, m, N);
    k_agg_max64<<<aggBlocks, 256>>>(m, agg, rowptr, csrc, N);
    k_gemm<64, 64, true, true><<<nblocks256, 256, smem_bytes(64, 64, true)>>>(
        x, W1_self, agg, W1_neigh, b1, h1, N);

    // ---- layer 2 (pool) ----
    k_gemm<64, 64, true, false><<<nblocks256, 256, smem_bytes(64, 64, false)>>>(
        h1, W2_pool, nullptr, nullptr, b2_pool, m, N);
    k_agg_max64<<<aggBlocks, 256>>>(m, agg, rowptr, csrc, N);
    k_gemm<64, 32, false, true><<<nblocks256, 256, smem_bytes(64, 32, true)>>>(
        h1, W2_self, agg, W2_neigh, b2, h2, N);

    // ---- layer 3 (mean) ----
    k_agg_mean32<<<aggBlocks, 256>>>(h2, agg3, rowptr, csrc, N);
    k_gemm<32, 32, false, true><<<nblocks256, 256, smem_bytes(32, 32, true)>>>(
        h2, W3_self, agg3, W3_neigh, b3, (float*)d_out, N);
}

// round 4
// speedup vs baseline: 1.0201x; 1.0201x over previous
#include <cuda_runtime.h>
#include <cstdint>

// Problem constants (fixed by the dataset)
#define MAXN 100000
#define MAXE 1600000

// ---------------- scratch (device globals; no allocs allowed) ----------------
__device__ float g_m[MAXN * 64];      // pool-transformed features
__device__ float g_agg[MAXN * 64];    // max-aggregated features
__device__ float g_h1[MAXN * 64];     // layer-1 output
__device__ float g_h2[MAXN * 32];     // layer-2 output
__device__ float g_agg3[MAXN * 32];   // layer-3 mean aggregate
__device__ int   g_rowptr[MAXN + 1];
__device__ int   g_deg[MAXN];         // degree, then reused as scatter cursor
__device__ int   g_scantmp[MAXN];
__device__ int   g_bsum[1024];
__device__ int   g_csrc[MAXE];        // CSR src ids, grouped by dst

// ---------------- f32x2 packed-FMA helpers (sm_100+) ----------------
__device__ __forceinline__ unsigned long long pk2(float lo, float hi) {
    unsigned long long r;
    asm("mov.b64 %0,{%1,%2};" : "=l"(r) : "f"(lo), "f"(hi));
    return r;
}
__device__ __forceinline__ void fma2(unsigned long long& d, unsigned long long a,
                                     unsigned long long b) {
    asm("fma.rn.f32x2 %0, %1, %2, %0;" : "+l"(d) : "l"(a), "l"(b));
}
__device__ __forceinline__ void upk2(unsigned long long v, float& lo, float& hi) {
    asm("mov.b64 {%0,%1},%2;" : "=f"(lo), "=f"(hi) : "l"(v));
}

// ---------------- CSR build ----------------
__global__ void k_zero_int(int* p, int n) {
    int i = blockIdx.x * blockDim.x + threadIdx.x;
    if (i < n) p[i] = 0;
}

__global__ void k_hist(const int* __restrict__ dst, int* __restrict__ deg, int E, int N) {
    int e = blockIdx.x * blockDim.x + threadIdx.x;
    if (e < E) {
        int d = dst[e];
        if (d >= 0 && d < N) atomicAdd(&deg[d], 1);
    }
}

// pass 1: per-block inclusive scan (512 elems / block)
__global__ void k_scan1(const int* __restrict__ deg, int* __restrict__ scantmp,
                        int* __restrict__ bsum, int n) {
    __shared__ int sh[512];
    int tid = threadIdx.x;
    int i = blockIdx.x * 512 + tid;
    int v = (i < n) ? deg[i] : 0;
    sh[tid] = v;
    __syncthreads();
#pragma unroll
    for (int off = 1; off < 512; off <<= 1) {
        int t = (tid >= off) ? sh[tid - off] : 0;
        __syncthreads();
        sh[tid] += t;
        __syncthreads();
    }
    if (i < n) scantmp[i] = sh[tid];
    if (tid == 511) bsum[blockIdx.x] = sh[511];
}

// pass 2: parallel exclusive scan of block sums (nb <= 256)
__global__ void k_scan2(int* bsum, int nb) {
    __shared__ int sh[256];
    int tid = threadIdx.x;
    int v = (tid < nb) ? bsum[tid] : 0;
    sh[tid] = v;
    __syncthreads();
#pragma unroll
    for (int off = 1; off < 256; off <<= 1) {
        int t = (tid >= off) ? sh[tid - off] : 0;
        __syncthreads();
        sh[tid] += t;
        __syncthreads();
    }
    if (tid < nb) bsum[tid] = sh[tid] - v;  // exclusive
}

// pass 3: exclusive rowptr + cursor init (deg array becomes cursor)
__global__ void k_scan3(const int* __restrict__ scantmp, int* __restrict__ deg_cursor,
                        int* __restrict__ rowptr, const int* __restrict__ bsum,
                        int n, int E) {
    int i = blockIdx.x * blockDim.x + threadIdx.x;
    if (i < n) {
        int d = deg_cursor[i];
        int ex = scantmp[i] - d + bsum[i >> 9];
        rowptr[i] = ex;
        deg_cursor[i] = ex;   // cursor
    }
    if (i == 0) rowptr[n] = E;
}

__global__ void k_scatter(const int* __restrict__ src, const int* __restrict__ dst,
                          int* __restrict__ cursor, int* __restrict__ csrc, int E, int N) {
    int e = blockIdx.x * blockDim.x + threadIdx.x;
    if (e < E) {
        int d = dst[e];
        if (d >= 0 && d < N) {
            int p = atomicAdd(&cursor[d], 1);
            csrc[p] = src[e];
        }
    }
}

// ---------------- aggregation (gather over CSR, warp per node) ----------------
// max over relu'd features (all >= 0 so init 0 matches reference incl. isolated nodes)
__global__ void k_agg_max64(const float* __restrict__ feat, float* __restrict__ out,
                            const int* __restrict__ rowptr, const int* __restrict__ srcs,
                            int n) {
    int v = blockIdx.x * (blockDim.x >> 5) + (threadIdx.x >> 5);
    if (v >= n) return;
    int lane = threadIdx.x & 31;
    int beg = rowptr[v], end = rowptr[v + 1];
    float a0 = 0.f, a1 = 0.f;
    int e = beg;
    for (; e + 3 < end; e += 4) {
        int s0 = __ldg(&srcs[e]);
        int s1 = __ldg(&srcs[e + 1]);
        int s2 = __ldg(&srcs[e + 2]);
        int s3 = __ldg(&srcs[e + 3]);
        const float* f0 = feat + (size_t)s0 * 64;
        const float* f1 = feat + (size_t)s1 * 64;
        const float* f2 = feat + (size_t)s2 * 64;
        const float* f3 = feat + (size_t)s3 * 64;
        float b0 = f0[lane], b1 = f0[lane + 32];
        float c0 = f1[lane], c1 = f1[lane + 32];
        float d0 = f2[lane], d1 = f2[lane + 32];
        float e0 = f3[lane], e1 = f3[lane + 32];
        a0 = fmaxf(a0, fmaxf(fmaxf(b0, c0), fmaxf(d0, e0)));
        a1 = fmaxf(a1, fmaxf(fmaxf(b1, c1), fmaxf(d1, e1)));
    }
    for (; e < end; e++) {
        int s0 = __ldg(&srcs[e]);
        const float* f0 = feat + (size_t)s0 * 64;
        a0 = fmaxf(a0, f0[lane]);
        a1 = fmaxf(a1, f0[lane + 32]);
    }
    out[(size_t)v * 64 + lane] = a0;
    out[(size_t)v * 64 + 32 + lane] = a1;
}

// mean over 32-dim features (count == degree == rowptr diff)
__global__ void k_agg_mean32(const float* __restrict__ feat, float* __restrict__ out,
                             const int* __restrict__ rowptr, const int* __restrict__ srcs,
                             int n) {
    int v = blockIdx.x * (blockDim.x >> 5) + (threadIdx.x >> 5);
    if (v >= n) return;
    int lane = threadIdx.x & 31;
    int beg = rowptr[v], end = rowptr[v + 1];
    float a = 0.f;
    int e = beg;
    for (; e + 3 < end; e += 4) {
        int s0 = __ldg(&srcs[e]);
        int s1 = __ldg(&srcs[e + 1]);
        int s2 = __ldg(&srcs[e + 2]);
        int s3 = __ldg(&srcs[e + 3]);
        float t0 = feat[(size_t)s0 * 32 + lane];
        float t1 = feat[(size_t)s1 * 32 + lane];
        float t2 = feat[(size_t)s2 * 32 + lane];
        float t3 = feat[(size_t)s3 * 32 + lane];
        a += (t0 + t1) + (t2 + t3);
    }
    for (; e < end; e++) {
        int s0 = __ldg(&srcs[e]);
        a += feat[(size_t)s0 * 32 + lane];
    }
    float cnt = (float)(end - beg);
    float inv = 1.f / fmaxf(cnt, 1.f);
    out[(size_t)v * 32 + lane] = a * inv;
}

// ---------------- fused node GEMM (f32x2 packed dual-FMA) ----------------
// out = [relu]( A@W1 [+ B@W2] + bias ), A/B: [n, IN] row-major, W: [IN, OUT] row-major
// 256 threads; 256 nodes/block; per-thread tile: 8 nodes x TJ outs (TJ = OUT/8).
// Inner loop steps k by 2; accumulators are f32x2 pairs over adjacent j.
template <int IN, int OUT, bool RELU, bool TWO>
__global__ void __launch_bounds__(256) k_gemm(const float* __restrict__ A,
                                              const float* __restrict__ W1,
                                              const float* __restrict__ B,
                                              const float* __restrict__ W2,
                                              const float* __restrict__ bias,
                                              float* __restrict__ out, int n) {
    constexpr int NPB = 256;
    constexpr int TJ = OUT / 8;    // outputs per thread
    constexpr int NP = TJ / 2;     // f32x2 pairs per thread
    constexpr int LDA = IN + 2;    // even: keeps float2 loads 8B-aligned
    extern __shared__ float sm[];
    float* sW1 = sm;                                // IN*OUT
    float* sW2 = TWO ? (sm + IN * OUT) : nullptr;   // IN*OUT
    float* sB = sm + IN * OUT * (TWO ? 2 : 1);      // OUT
    float* sA = sB + OUT;                           // NPB*LDA

    int tid = threadIdx.x;
    for (int i = tid; i < IN * OUT; i += 256) {
        sW1[i] = W1[i];
        if (TWO) sW2[i] = W2[i];
    }
    for (int i = tid; i < OUT; i += 256) sB[i] = bias[i];

    int base = blockIdx.x * NPB;
    for (int i = tid; i < NPB * IN; i += 256) {
        int nn = i / IN, kk = i % IN;
        sA[nn * LDA + kk] = (base + nn < n) ? A[(size_t)(base + nn) * IN + kk] : 0.f;
    }
    __syncthreads();

    int jg = tid & 7;
    int ng = tid >> 3;  // 0..31, each owns 8 nodes
    unsigned long long acc2[8][NP];
#pragma unroll
    for (int i = 0; i < 8; i++)
#pragma unroll
        for (int j = 0; j < NP; j++) acc2[i][j] = 0ull;

    const float* sAr = sA + (ng * 8) * LDA;
    {
        const float* sW = sW1;
#pragma unroll 4
        for (int k = 0; k < IN; k += 2) {
            float2 xv[8];
#pragma unroll
            for (int i = 0; i < 8; i++)
                xv[i] = *reinterpret_cast<const float2*>(&sAr[i * LDA + k]);
            unsigned long long wv0[NP], wv1[NP];
#pragma unroll
            for (int j = 0; j < NP; j++) {
                wv0[j] = *reinterpret_cast<const unsigned long long*>(
                    &sW[k * OUT + jg * TJ + 2 * j]);
                wv1[j] = *reinterpret_cast<const unsigned long long*>(
                    &sW[(k + 1) * OUT + jg * TJ + 2 * j]);
            }
#pragma unroll
            for (int i = 0; i < 8; i++) {
                unsigned long long a0 = pk2(xv[i].x, xv[i].x);
                unsigned long long a1 = pk2(xv[i].y, xv[i].y);
#pragma unroll
                for (int j = 0; j < NP; j++) {
                    fma2(acc2[i][j], a0, wv0[j]);
                    fma2(acc2[i][j], a1, wv1[j]);
                }
            }
        }
    }

    if (TWO) {
        __syncthreads();
        for (int i = tid; i < NPB * IN; i += 256) {
            int nn = i / IN, kk = i % IN;
            sA[nn * LDA + kk] = (base + nn < n) ? B[(size_t)(base + nn) * IN + kk] : 0.f;
        }
        __syncthreads();
        const float* sW = sW2;
#pragma unroll 4
        for (int k = 0; k < IN; k += 2) {
            float2 xv[8];
#pragma unroll
            for (int i = 0; i < 8; i++)
                xv[i] = *reinterpret_cast<const float2*>(&sAr[i * LDA + k]);
            unsigned long long wv0[NP], wv1[NP];
#pragma unroll
            for (int j = 0; j < NP; j++) {
                wv0[j] = *reinterpret_cast<const unsigned long long*>(
                    &sW[k * OUT + jg * TJ + 2 * j]);
                wv1[j] = *reinterpret_cast<const unsigned long long*>(
                    &sW[(k + 1) * OUT + jg * TJ + 2 * j]);
            }
#pragma unroll
            for (int i = 0; i < 8; i++) {
                unsigned long long a0 = pk2(xv[i].x, xv[i].x);
                unsigned long long a1 = pk2(xv[i].y, xv[i].y);
#pragma unroll
                for (int j = 0; j < NP; j++) {
                    fma2(acc2[i][j], a0, wv0[j]);
                    fma2(acc2[i][j], a1, wv1[j]);
                }
            }
        }
    }

#pragma unroll
    for (int i = 0; i < 8; i++) {
        int node = base + ng * 8 + i;
        if (node < n) {
#pragma unroll
            for (int j = 0; j < NP; j++) {
                float lo, hi;
                upk2(acc2[i][j], lo, hi);
                float v0 = lo + sB[jg * TJ + 2 * j];
                float v1 = hi + sB[jg * TJ + 2 * j + 1];
                if (RELU) { v0 = fmaxf(v0, 0.f); v1 = fmaxf(v1, 0.f); }
                out[(size_t)node * OUT + jg * TJ + 2 * j] = v0;
                out[(size_t)node * OUT + jg * TJ + 2 * j + 1] = v1;
            }
        }
    }
}

// ---------------- host launch ----------------
static inline int smem_bytes(int IN, int OUT, bool TWO) {
    return (IN * OUT * (TWO ? 2 : 1) + OUT + 256 * (IN + 2)) * (int)sizeof(float);
}

extern "C" void kernel_launch(void* const* d_in, const int* in_sizes, int n_in,
                              void* d_out, int out_size) {
    const float* x        = (const float*)d_in[0];
    const int*   ei       = (const int*)d_in[1];   // int32 (JAX x64 disabled)
    const float* W1_pool  = (const float*)d_in[2];
    const float* b1_pool  = (const float*)d_in[3];
    const float* W1_self  = (const float*)d_in[4];
    const float* W1_neigh = (const float*)d_in[5];
    const float* b1       = (const float*)d_in[6];
    const float* W2_pool  = (const float*)d_in[7];
    const float* b2_pool  = (const float*)d_in[8];
    const float* W2_self  = (const float*)d_in[9];
    const float* W2_neigh = (const float*)d_in[10];
    const float* b2       = (const float*)d_in[11];
    const float* W3_self  = (const float*)d_in[12];
    const float* W3_neigh = (const float*)d_in[13];
    const float* b3       = (const float*)d_in[14];

    int N = in_sizes[0] / 64;
    int E = in_sizes[1] / 2;
    if (N > MAXN) N = MAXN;
    if (E > MAXE) E = MAXE;

    const int* src = ei;        // row 0
    const int* dst = ei + E;    // row 1

    // scratch pointers
    float *m, *agg, *h1, *h2, *agg3;
    int *rowptr, *deg, *scantmp, *bsum, *csrc;
    cudaGetSymbolAddress((void**)&m, g_m);
    cudaGetSymbolAddress((void**)&agg, g_agg);
    cudaGetSymbolAddress((void**)&h1, g_h1);
    cudaGetSymbolAddress((void**)&h2, g_h2);
    cudaGetSymbolAddress((void**)&agg3, g_agg3);
    cudaGetSymbolAddress((void**)&rowptr, g_rowptr);
    cudaGetSymbolAddress((void**)&deg, g_deg);
    cudaGetSymbolAddress((void**)&scantmp, g_scantmp);
    cudaGetSymbolAddress((void**)&bsum, g_bsum);
    cudaGetSymbolAddress((void**)&csrc, g_csrc);

    // dynamic smem attributes for GEMM instantiations (idempotent)
    cudaFuncSetAttribute((const void*)k_gemm<64, 64, true, false>,
                         cudaFuncAttributeMaxDynamicSharedMemorySize, smem_bytes(64, 64, false));
    cudaFuncSetAttribute((const void*)k_gemm<64, 64, true, true>,
                         cudaFuncAttributeMaxDynamicSharedMemorySize, smem_bytes(64, 64, true));
    cudaFuncSetAttribute((const void*)k_gemm<64, 32, false, true>,
                         cudaFuncAttributeMaxDynamicSharedMemorySize, smem_bytes(64, 32, true));
    cudaFuncSetAttribute((const void*)k_gemm<32, 32, false, true>,
                         cudaFuncAttributeMaxDynamicSharedMemorySize, smem_bytes(32, 32, true));

    int ethreads = 256;
    int eblocks = (E + ethreads - 1) / ethreads;
    int nblocks256 = (N + 255) / 256;
    int nbScan = (N + 511) / 512;
    int aggBlocks = (N + 7) / 8;  // 8 warps / block

    // ---- CSR build ----
    k_zero_int<<<nblocks256, 256>>>(deg, N);
    k_hist<<<eblocks, ethreads>>>(dst, deg, E, N);
    k_scan1<<<nbScan, 512>>>(deg, scantmp, bsum, N);
    k_scan2<<<1, 256>>>(bsum, nbScan);
    k_scan3<<<nblocks256, 256>>>(scantmp, deg, rowptr, bsum, N, E);
    k_scatter<<<eblocks, ethreads>>>(src, dst, deg, csrc, E, N);

    // ---- layer 1 (pool) ----
    k_gemm<64, 64, true, false><<<nblocks256, 256, smem_bytes(64, 64, false)>>>(
        x, W1_pool, nullptr, nullptr, b1_pool, m, N);
    k_agg_max64<<<aggBlocks, 256>>>(m, agg, rowptr, csrc, N);
    k_gemm<64, 64, true, true><<<nblocks256, 256, smem_bytes(64, 64, true)>>>(
        x, W1_self, agg, W1_neigh, b1, h1, N);

    // ---- layer 2 (pool) ----
    k_gemm<64, 64, true, false><<<nblocks256, 256, smem_bytes(64, 64, false)>>>(
        h1, W2_pool, nullptr, nullptr, b2_pool, m, N);
    k_agg_max64<<<aggBlocks, 256>>>(m, agg, rowptr, csrc, N);
    k_gemm<64, 32, false, true><<<nblocks256, 256, smem_bytes(64, 32, true)>>>(
        h1, W2_self, agg, W2_neigh, b2, h2, N);

    // ---- layer 3 (mean) ----
    k_agg_mean32<<<aggBlocks, 256>>>(h2, agg3, rowptr, csrc, N);
    k_gemm<32, 32, false, true><<<nblocks256, 256, smem_bytes(32, 32, true)>>>(
        h2, W3_self, agg3, W3_neigh, b3, (float*)d_out, N);
}